// round 15
// baseline (speedup 1.0000x reference)
#include <cuda_runtime.h>
#include <cuda_bf16.h>
#include <cstdint>

#define N_Q   16384
#define DIMS  64
#define K_CB  8192
#define MT    128            // queries per CTA
#define NT    128            // codewords per tile
#define NTILES (K_CB / NT)   // 64
#define THREADS 512
#define TAU 2.5f

// padded bf16 row: 64 elems + 8 pad = 72 elems = 144 bytes
#define ROWB 144
#define TERM_BYTES (128 * ROWB)      // 18432 per tile (128 rows)
#define STAGE (TERM_BYTES + 512)     // tile + csq = 18944

// shared memory layout (bytes)
#define SM_B     0                       // 4 stages x 18944 = 75776
#define SM_A     75776                   // 18432
#define SM_CAND  94208                   // 128 q x 48 slots x 8B = 49152
#define SM_BESTK 143360                  // 128 ints
#define SMEM_TOTAL 143872

__device__ __nv_bfloat16 g_enc_bf[N_Q * DIMS];
__device__ __nv_bfloat16 g_cb_bf[K_CB * DIMS];
__device__ __align__(16) float g_csq[K_CB];

// ---------------- helpers ----------------
__device__ __forceinline__ uint32_t smem_u32(const void* p) {
    uint32_t a;
    asm("{ .reg .u64 t; cvta.to.shared.u64 t, %1; cvt.u32.u64 %0, t; }" : "=r"(a) : "l"(p));
    return a;
}
#define CP16(d, s)  asm volatile("cp.async.cg.shared.global [%0], [%1], 16;" :: "r"(d), "l"(s))
#define CP_COMMIT() asm volatile("cp.async.commit_group;" ::: "memory")
#define CP_WAIT2()  asm volatile("cp.async.wait_group 2;" ::: "memory")
#define BAR_GRP(id) asm volatile("bar.sync %0, 128;" :: "r"(id) : "memory")

__device__ __forceinline__ void ldsm_x4(uint32_t* r, uint32_t addr) {
    asm volatile("ldmatrix.sync.aligned.m8n8.x4.shared.b16 {%0,%1,%2,%3}, [%4];"
                 : "=r"(r[0]), "=r"(r[1]), "=r"(r[2]), "=r"(r[3]) : "r"(addr));
}
__device__ __forceinline__ void mma16816(float* c, const uint32_t* a, const uint32_t* b) {
    asm volatile("mma.sync.aligned.m16n8k16.row.col.f32.bf16.bf16.f32 "
                 "{%0,%1,%2,%3}, {%4,%5,%6,%7}, {%8,%9}, {%0,%1,%2,%3};"
                 : "+f"(c[0]), "+f"(c[1]), "+f"(c[2]), "+f"(c[3])
                 : "r"(a[0]), "r"(a[1]), "r"(a[2]), "r"(a[3]), "r"(b[0]), "r"(b[1]));
}

// ---------------- preprocessing ----------------
__global__ void prep_kernel(const float* __restrict__ enc, const float* __restrict__ cb) {
    int idx = blockIdx.x * blockDim.x + threadIdx.x;     // one float4
    const int n4e = N_Q * DIMS / 4;
    const float4* src;
    __nv_bfloat162* ph;
    int j;
    if (idx < n4e) { src = (const float4*)enc; j = idx; ph = (__nv_bfloat162*)g_enc_bf; }
    else           { src = (const float4*)cb;  j = idx - n4e; ph = (__nv_bfloat162*)g_cb_bf; }
    float4 v = src[j];
    __nv_bfloat162 a; a.x = __float2bfloat16(v.x); a.y = __float2bfloat16(v.y);
    __nv_bfloat162 b; b.x = __float2bfloat16(v.z); b.y = __float2bfloat16(v.w);
    ph[j * 2] = a; ph[j * 2 + 1] = b;
}

__global__ void csq_kernel(const float* __restrict__ cb) {
    int row  = blockIdx.x * 8 + (threadIdx.x >> 5);
    int lane = threadIdx.x & 31;
    float v0 = cb[row * DIMS + lane];
    float v1 = cb[row * DIMS + 32 + lane];
    float s  = v0 * v0 + v1 * v1;
    #pragma unroll
    for (int off = 16; off; off >>= 1) s += __shfl_xor_sync(0xffffffffu, s, off);
    if (lane == 0) g_csq[row] = s;
}

// ---------------- strip loader: group wn loads rows [32wn, 32wn+32) ----------------
__device__ __forceinline__ void load_B_strip(uint32_t smem_base, int tile, int stage,
                                             int wn, int gtid) {
    const int kb = tile * NT;
    #pragma unroll
    for (int u = 0; u < 2; ++u) {
        int c = gtid * 2 + u;             // 0..255
        int r = wn * 32 + (c >> 3);       // row within tile
        int q = c & 7;                    // 16B chunk
        const char* src = (const char*)g_cb_bf + (size_t)(kb + r) * 128 + q * 16;
        uint32_t dst = smem_base + SM_B + stage * STAGE + r * ROWB + q * 16;
        CP16(dst, src);
    }
    if (gtid < 8) {
        uint32_t dst = smem_base + SM_B + stage * STAGE + TERM_BYTES + wn * 128 + gtid * 16;
        CP16(dst, (const char*)g_csq + (size_t)kb * 4 + wn * 128 + gtid * 16);
    }
}

// ---------------- main kernel ----------------
__global__ __launch_bounds__(THREADS, 1)
void vq_main(const float* __restrict__ enc, const float* __restrict__ cb,
             float* __restrict__ out)
{
    extern __shared__ char smem[];
    const uint32_t smem_base = smem_u32(smem);
    const int tid  = threadIdx.x;
    const int wid  = tid >> 5;
    const int lane = tid & 31;
    const int wm   = wid & 3;             // 4 warps over M (32 rows each)
    const int wn   = wid >> 2;            // 4 warps over N (32 cols each) == tid>>7
    const int gtid = tid & 127;           // rank within wn-group
    const int m0   = blockIdx.x * MT;

    // ---- prologue: strips for tiles 0..2 ----
    load_B_strip(smem_base, 0, 0, wn, gtid); CP_COMMIT();
    load_B_strip(smem_base, 1, 1, wn, gtid); CP_COMMIT();
    load_B_strip(smem_base, 2, 2, wn, gtid); CP_COMMIT();

    // ---- stage A (bf16), padded rows ----
    #pragma unroll
    for (int i = 0; i < 2; ++i) {
        int c = tid + i * THREADS;        // 0..1023
        int r = c >> 3;
        int q = c & 7;
        const uint4* src = (const uint4*)(g_enc_bf + (size_t)(m0 + r) * DIMS) + q;
        *(uint4*)(smem + SM_A + r * ROWB + q * 16) = *src;
    }
    __syncthreads();

    const uint32_t a_base = smem_base + SM_A
        + (wm * 32 + (lane & 15)) * ROWB + ((lane >> 4) & 1) * 16;
    const uint32_t b_base = smem_base + SM_B
        + (wn * 32 + (lane >> 4) * 8 + (lane & 7)) * ROWB + ((lane >> 3) & 1) * 16;

    // ---- hoist A fragments (tile-invariant) ----
    uint32_t af[4][2][4];                 // [ks][i][frag]
    #pragma unroll
    for (int ks = 0; ks < 4; ++ks)
        #pragma unroll
        for (int i = 0; i < 2; ++i)
            ldsm_x4(af[ks][i], a_base + i * 16 * ROWB + ks * 32);

    float bm1[4], bm2[4], bm3[4];
    int   bi1[4], bi2[4], bi3[4];
    #pragma unroll
    for (int r = 0; r < 4; ++r) {
        bm1[r] = 3.4e38f; bm2[r] = 3.4e38f; bm3[r] = 3.4e38f;
        bi1[r] = 0; bi2[r] = 0; bi3[r] = 0;
    }

    float acc[2][4][4];
    const int bar_id = 1 + wn;

    for (int t = 0; t < NTILES; ++t) {
        const int stage = t & 3;
        CP_WAIT2();                       // own groups for tile t done
        BAR_GRP(bar_id);                  // group-local: peers' strip loads visible;
                                          // stage (t+3)&3 strip fully consumed by group
        if (t + 3 < NTILES) load_B_strip(smem_base, t + 3, (t + 3) & 3, wn, gtid);
        CP_COMMIT();

        #pragma unroll
        for (int i = 0; i < 2; ++i)
            #pragma unroll
            for (int j = 0; j < 4; ++j)
                #pragma unroll
                for (int r = 0; r < 4; ++r) acc[i][j][r] = 0.f;

        const uint32_t bs = b_base + stage * STAGE;
        #pragma unroll
        for (int ks = 0; ks < 4; ++ks) {
            uint32_t bh[4][2];
            {
                uint32_t r0[4], r1[4];
                ldsm_x4(r0, bs + ks * 32);
                ldsm_x4(r1, bs + 16 * ROWB + ks * 32);
                bh[0][0] = r0[0]; bh[0][1] = r0[1];
                bh[1][0] = r0[2]; bh[1][1] = r0[3];
                bh[2][0] = r1[0]; bh[2][1] = r1[1];
                bh[3][0] = r1[2]; bh[3][1] = r1[3];
            }
            #pragma unroll
            for (int i = 0; i < 2; ++i)
                #pragma unroll
                for (int j = 0; j < 4; ++j) mma16816(acc[i][j], af[ks][i], bh[j]);
        }

        // ---- gated argmin epilogue ----
        const int kb = t * NT;
        float csx[4], csy[4];
        #pragma unroll
        for (int j = 0; j < 4; ++j) {
            float2 cs = *(const float2*)(smem + SM_B + stage * STAGE + TERM_BYTES
                        + (wn * 32 + j * 8 + (lane & 3) * 2) * 4);
            csx[j] = cs.x; csy[j] = cs.y;
        }
        #pragma unroll
        for (int i = 0; i < 2; ++i) {
            #pragma unroll
            for (int h = 0; h < 2; ++h) {
                const int ri = i * 2 + h;
                float rmin = 3.4e38f;
                #pragma unroll
                for (int j = 0; j < 4; ++j) {
                    float m0v = fmaf(-2.f, acc[i][j][h * 2 + 0], csx[j]);
                    float m1v = fmaf(-2.f, acc[i][j][h * 2 + 1], csy[j]);
                    rmin = fminf(rmin, fminf(m0v, m1v));
                }
                if (rmin < bm3[ri]) {
                    // rare path: full insert scan in ascending-k order
                    #pragma unroll
                    for (int j = 0; j < 4; ++j) {
                        const int k0 = kb + wn * 32 + j * 8 + (lane & 3) * 2;
                        #pragma unroll
                        for (int c = 0; c < 2; ++c) {
                            float m = fmaf(-2.f, acc[i][j][h * 2 + c], c ? csy[j] : csx[j]);
                            const int k = k0 + c;
                            if (m < bm3[ri]) {
                                if (m < bm1[ri]) {
                                    bm3[ri] = bm2[ri]; bi3[ri] = bi2[ri];
                                    bm2[ri] = bm1[ri]; bi2[ri] = bi1[ri];
                                    bm1[ri] = m;       bi1[ri] = k;
                                } else if (m < bm2[ri]) {
                                    bm3[ri] = bm2[ri]; bi3[ri] = bi2[ri];
                                    bm2[ri] = m;       bi2[ri] = k;
                                } else {
                                    bm3[ri] = m;       bi3[ri] = k;
                                }
                            }
                        }
                    }
                }
            }
        }
    }

    // ---- candidate dump: 16 slices x 3 (m, k) per query ----
    __syncthreads();
    {
        float2* cand = (float2*)(smem + SM_CAND);
        const int slot = wn * 4 + (lane & 3);            // 0..15
        #pragma unroll
        for (int i = 0; i < 2; ++i)
            #pragma unroll
            for (int h = 0; h < 2; ++h) {
                const int ri = i * 2 + h;
                const int q  = wm * 32 + i * 16 + h * 8 + (lane >> 2);
                float2* p = &cand[q * 48 + slot * 3];
                p[0] = make_float2(bm1[ri], __int_as_float(bi1[ri]));
                p[1] = make_float2(bm2[ri], __int_as_float(bi2[ri]));
                p[2] = make_float2(bm3[ri], __int_as_float(bi3[ri]));
            }
    }
    __syncthreads();

    // ---- margin-gated exact fp32 rescore: one warp per query ----
    {
        const float2* cand = (const float2*)(smem + SM_CAND);
        int* bestk = (int*)(smem + SM_BESTK);
        for (int it = 0; it < 8; ++it) {
            const int q = wid * 8 + it;
            float2 c0 = cand[q * 48 + lane];
            float2 c1 = (lane < 16) ? cand[q * 48 + 32 + lane]
                                    : make_float2(3.4e38f, __int_as_float(0));
            float lm = fminf(c0.x, c1.x);
            #pragma unroll
            for (int off = 16; off; off >>= 1)
                lm = fminf(lm, __shfl_xor_sync(0xffffffffu, lm, off));
            const float thresh = lm + TAU;

            const float4* er = (const float4*)(enc + (size_t)(m0 + q) * DIMS);
            float bm = 3.4e38f; int bk = 0x7fffffff;
            #pragma unroll
            for (int rnd = 0; rnd < 2; ++rnd) {
                float2 cc = rnd ? c1 : c0;
                if (cc.x <= thresh) {
                    const int k = __float_as_int(cc.y);
                    const float4* cr = (const float4*)(cb + (size_t)k * DIMS);
                    float s = 0.f;
                    #pragma unroll
                    for (int u = 0; u < 16; ++u) {
                        float4 a = er[u], b = cr[u];
                        s = fmaf(a.x, b.x, s); s = fmaf(a.y, b.y, s);
                        s = fmaf(a.z, b.z, s); s = fmaf(a.w, b.w, s);
                    }
                    float m = fmaf(-2.f, s, g_csq[k]);
                    if (m < bm || (m == bm && k < bk)) { bm = m; bk = k; }
                }
            }
            #pragma unroll
            for (int off = 16; off; off >>= 1) {
                float om = __shfl_xor_sync(0xffffffffu, bm, off);
                int   ok = __shfl_xor_sync(0xffffffffu, bk, off);
                if (om < bm || (om == bm && ok < bk)) { bm = om; bk = ok; }
            }
            if (lane == 0) bestk[q] = bk;
        }
    }
    __syncthreads();

    // ---- gather output rows ----
    {
        const int* bestk = (const int*)(smem + SM_BESTK);
        const float4* cb4 = (const float4*)cb;
        float4* out4 = (float4*)out;
        #pragma unroll
        for (int i = 0; i < 4; ++i) {
            int lin = tid + i * THREADS;            // 0..2047
            int q = lin >> 4;
            int quad = lin & 15;
            out4[(size_t)(m0 + q) * 16 + quad] = cb4[(size_t)bestk[q] * 16 + quad];
        }
    }
}

extern "C" void kernel_launch(void* const* d_in, const int* in_sizes, int n_in,
                              void* d_out, int out_size) {
    const float* enc = (const float*)d_in[0];
    const float* cb  = (const float*)d_in[1];
    if (n_in >= 2 && in_sizes[0] == K_CB * DIMS && in_sizes[1] == N_Q * DIMS) {
        enc = (const float*)d_in[1];
        cb  = (const float*)d_in[0];
    }
    float* out = (float*)d_out;

    cudaFuncSetAttribute(vq_main, cudaFuncAttributeMaxDynamicSharedMemorySize, SMEM_TOTAL);

    prep_kernel<<<(N_Q * DIMS + K_CB * DIMS) / 4 / 256, 256>>>(enc, cb);
    csq_kernel<<<K_CB / 8, 256>>>(cb);
    vq_main<<<N_Q / MT, THREADS, SMEM_TOTAL>>>(enc, cb, out);
}

// round 16
// speedup vs baseline: 1.6093x; 1.6093x over previous
#include <cuda_runtime.h>
#include <cuda_bf16.h>
#include <cstdint>

#define N_Q   16384
#define DIMS  64
#define K_CB  8192
#define MT    128            // queries per CTA
#define NT    128            // codewords per tile
#define NTILES (K_CB / NT)   // 64
#define THREADS 512
#define TAU 2.5f

// padded bf16 row: 64 elems + 8 pad = 72 elems = 144 bytes
#define ROWB 144
#define TERM_BYTES (128 * ROWB)      // 18432 per tile (128 rows)
#define STAGE (TERM_BYTES + 512)     // tile + csq = 18944

// shared memory layout (bytes)
#define SM_B     0                       // 4 stages x 18944 = 75776
#define SM_A     75776                   // 18432
#define SM_CAND  94208                   // 128 q x 48 slots x 8B = 49152
#define SM_BESTK 143360                  // 128 ints
#define SMEM_TOTAL 143872

// fused prep grid split
#define CONV_BLOCKS ((N_Q * DIMS + K_CB * DIMS) / 4 / 256)   // 1536
#define CSQ_BLOCKS  (K_CB / 8)                               // 1024

__device__ __nv_bfloat16 g_enc_bf[N_Q * DIMS];
__device__ __nv_bfloat16 g_cb_bf[K_CB * DIMS];
__device__ __align__(16) float g_csq[K_CB];

// ---------------- helpers ----------------
__device__ __forceinline__ uint32_t smem_u32(const void* p) {
    uint32_t a;
    asm("{ .reg .u64 t; cvta.to.shared.u64 t, %1; cvt.u32.u64 %0, t; }" : "=r"(a) : "l"(p));
    return a;
}
#define CP16(d, s)  asm volatile("cp.async.cg.shared.global [%0], [%1], 16;" :: "r"(d), "l"(s))
#define CP_COMMIT() asm volatile("cp.async.commit_group;" ::: "memory")
#define CP_WAIT2()  asm volatile("cp.async.wait_group 2;" ::: "memory")

__device__ __forceinline__ void ldsm_x4(uint32_t* r, uint32_t addr) {
    asm volatile("ldmatrix.sync.aligned.m8n8.x4.shared.b16 {%0,%1,%2,%3}, [%4];"
                 : "=r"(r[0]), "=r"(r[1]), "=r"(r[2]), "=r"(r[3]) : "r"(addr));
}
__device__ __forceinline__ void mma16816(float* c, const uint32_t* a, const uint32_t* b) {
    asm volatile("mma.sync.aligned.m16n8k16.row.col.f32.bf16.bf16.f32 "
                 "{%0,%1,%2,%3}, {%4,%5,%6,%7}, {%8,%9}, {%0,%1,%2,%3};"
                 : "+f"(c[0]), "+f"(c[1]), "+f"(c[2]), "+f"(c[3])
                 : "r"(a[0]), "r"(a[1]), "r"(a[2]), "r"(a[3]), "r"(b[0]), "r"(b[1]));
}

// ---------------- fused preprocessing: convert + csq in one launch ----------------
__global__ void prep_kernel(const float* __restrict__ enc, const float* __restrict__ cb) {
    if (blockIdx.x < CONV_BLOCKS) {
        int idx = blockIdx.x * blockDim.x + threadIdx.x;     // one float4
        const int n4e = N_Q * DIMS / 4;
        const float4* src;
        __nv_bfloat162* ph;
        int j;
        if (idx < n4e) { src = (const float4*)enc; j = idx; ph = (__nv_bfloat162*)g_enc_bf; }
        else           { src = (const float4*)cb;  j = idx - n4e; ph = (__nv_bfloat162*)g_cb_bf; }
        float4 v = src[j];
        __nv_bfloat162 a; a.x = __float2bfloat16(v.x); a.y = __float2bfloat16(v.y);
        __nv_bfloat162 b; b.x = __float2bfloat16(v.z); b.y = __float2bfloat16(v.w);
        ph[j * 2] = a; ph[j * 2 + 1] = b;
    } else {
        int row  = (blockIdx.x - CONV_BLOCKS) * 8 + (threadIdx.x >> 5);
        int lane = threadIdx.x & 31;
        float v0 = cb[row * DIMS + lane];
        float v1 = cb[row * DIMS + 32 + lane];
        float s  = v0 * v0 + v1 * v1;
        #pragma unroll
        for (int off = 16; off; off >>= 1) s += __shfl_xor_sync(0xffffffffu, s, off);
        if (lane == 0) g_csq[row] = s;
    }
}

// ---------------- B tile loader ----------------
__device__ __forceinline__ void load_B_tile(uint32_t smem_base, int tile, int stage, int tid) {
    const int kb = tile * NT;
    #pragma unroll
    for (int i = 0; i < 2; ++i) {
        int c = tid + i * THREADS;        // 0..1023
        int r = c >> 3;                   // codeword row within tile
        int q = c & 7;                    // 16B chunk
        const char* src = (const char*)g_cb_bf + (size_t)(kb + r) * 128 + q * 16;
        uint32_t dst = smem_base + SM_B + stage * STAGE + r * ROWB + q * 16;
        CP16(dst, src);
    }
    if (tid < 32) {
        uint32_t dst = smem_base + SM_B + stage * STAGE + TERM_BYTES + tid * 16;
        CP16(dst, (const char*)g_csq + (size_t)kb * 4 + tid * 16);
    }
}

// ---------------- main kernel ----------------
__global__ __launch_bounds__(THREADS, 1)
void vq_main(const float* __restrict__ enc, const float* __restrict__ cb,
             float* __restrict__ out)
{
    extern __shared__ char smem[];
    const uint32_t smem_base = smem_u32(smem);
    const int tid  = threadIdx.x;
    const int wid  = tid >> 5;
    const int lane = tid & 31;
    const int wm   = wid & 3;             // 4 warps over M (32 rows each)
    const int wn   = wid >> 2;            // 4 warps over N (32 cols each)
    const int m0   = blockIdx.x * MT;

    // ---- start B pipeline immediately (stages 0..2) ----
    load_B_tile(smem_base, 0, 0, tid); CP_COMMIT();
    load_B_tile(smem_base, 1, 1, tid); CP_COMMIT();
    load_B_tile(smem_base, 2, 2, tid); CP_COMMIT();

    // ---- stage A (bf16), padded rows ----
    #pragma unroll
    for (int i = 0; i < 2; ++i) {
        int c = tid + i * THREADS;        // 0..1023
        int r = c >> 3;
        int q = c & 7;
        const uint4* src = (const uint4*)(g_enc_bf + (size_t)(m0 + r) * DIMS) + q;
        *(uint4*)(smem + SM_A + r * ROWB + q * 16) = *src;
    }
    CP_WAIT2();                           // tile 0 arrived (own thread)
    __syncthreads();                      // A + tile 0 visible to all warps

    // ldmatrix base addresses
    const uint32_t a_base = smem_base + SM_A
        + (wm * 32 + (lane & 15)) * ROWB + ((lane >> 4) & 1) * 16;
    const uint32_t b_base = smem_base + SM_B
        + (wn * 32 + (lane >> 4) * 8 + (lane & 7)) * ROWB + ((lane >> 3) & 1) * 16;

    // ---- hoist A fragments (tile-invariant): 2 m16 tiles x 4 ks ----
    uint32_t af[4][2][4];                 // [ks][i][frag]
    #pragma unroll
    for (int ks = 0; ks < 4; ++ks)
        #pragma unroll
        for (int i = 0; i < 2; ++i)
            ldsm_x4(af[ks][i], a_base + i * 16 * ROWB + ks * 32);

    // top-3 per owned query row (4 rows/thread)
    float bm1[4], bm2[4], bm3[4];
    int   bi1[4], bi2[4], bi3[4];
    #pragma unroll
    for (int r = 0; r < 4; ++r) {
        bm1[r] = 3.4e38f; bm2[r] = 3.4e38f; bm3[r] = 3.4e38f;
        bi1[r] = 0; bi2[r] = 0; bi3[r] = 0;
    }

    float acc[2][4][4];

    // Loop invariant at top of iter t: stage t&3 data visible to all warps.
    for (int t = 0; t < NTILES; ++t) {
        const int stage = t & 3;
        // prefetch tile t+3 into stage (t-1)&3: its readers (iter t-1 ldsm+csq)
        // all completed before the iter-(t-1) barrier below.
        if (t + 3 < NTILES) load_B_tile(smem_base, t + 3, (t + 3) & 3, tid);
        CP_COMMIT();

        #pragma unroll
        for (int i = 0; i < 2; ++i)
            #pragma unroll
            for (int j = 0; j < 4; ++j)
                #pragma unroll
                for (int r = 0; r < 4; ++r) acc[i][j][r] = 0.f;

        const uint32_t bs = b_base + stage * STAGE;
        #pragma unroll
        for (int ks = 0; ks < 4; ++ks) {
            uint32_t bh[4][2];
            {
                uint32_t r0[4], r1[4];
                ldsm_x4(r0, bs + ks * 32);
                ldsm_x4(r1, bs + 16 * ROWB + ks * 32);
                bh[0][0] = r0[0]; bh[0][1] = r0[1];
                bh[1][0] = r0[2]; bh[1][1] = r0[3];
                bh[2][0] = r1[0]; bh[2][1] = r1[1];
                bh[3][0] = r1[2]; bh[3][1] = r1[3];
            }
            #pragma unroll
            for (int i = 0; i < 2; ++i)
                #pragma unroll
                for (int j = 0; j < 4; ++j) mma16816(acc[i][j], af[ks][i], bh[j]);
        }

        // ---- csq loads (last smem reads of this stage) ----
        float csx[4], csy[4];
        #pragma unroll
        for (int j = 0; j < 4; ++j) {
            float2 cs = *(const float2*)(smem + SM_B + stage * STAGE + TERM_BYTES
                        + (wn * 32 + j * 8 + (lane & 3) * 2) * 4);
            csx[j] = cs.x; csy[j] = cs.y;
        }

        CP_WAIT2();                       // tile t+1 arrived (own thread)
        __syncthreads();                  // all smem reads of stage t done; t+1 visible

        // ---- insert chains AFTER the barrier: register-only, skew absorbed ----
        const int kb = t * NT;
        #pragma unroll
        for (int j = 0; j < 4; ++j) {
            const int k0 = kb + wn * 32 + j * 8 + (lane & 3) * 2;
            #pragma unroll
            for (int i = 0; i < 2; ++i) {
                #pragma unroll
                for (int h = 0; h < 2; ++h) {
                    const int ri = i * 2 + h;
                    #pragma unroll
                    for (int c = 0; c < 2; ++c) {
                        float m = fmaf(-2.f, acc[i][j][h * 2 + c], c ? csy[j] : csx[j]);
                        const int k = k0 + c;
                        if (m < bm3[ri]) {
                            if (m < bm1[ri]) {
                                bm3[ri] = bm2[ri]; bi3[ri] = bi2[ri];
                                bm2[ri] = bm1[ri]; bi2[ri] = bi1[ri];
                                bm1[ri] = m;       bi1[ri] = k;
                            } else if (m < bm2[ri]) {
                                bm3[ri] = bm2[ri]; bi3[ri] = bi2[ri];
                                bm2[ri] = m;       bi2[ri] = k;
                            } else {
                                bm3[ri] = m;       bi3[ri] = k;
                            }
                        }
                    }
                }
            }
        }
    }

    // ---- candidate dump: 16 slices x 3 (m, k) per query ----
    __syncthreads();
    {
        float2* cand = (float2*)(smem + SM_CAND);
        const int slot = wn * 4 + (lane & 3);            // 0..15
        #pragma unroll
        for (int i = 0; i < 2; ++i)
            #pragma unroll
            for (int h = 0; h < 2; ++h) {
                const int ri = i * 2 + h;
                const int q  = wm * 32 + i * 16 + h * 8 + (lane >> 2);
                float2* p = &cand[q * 48 + slot * 3];
                p[0] = make_float2(bm1[ri], __int_as_float(bi1[ri]));
                p[1] = make_float2(bm2[ri], __int_as_float(bi2[ri]));
                p[2] = make_float2(bm3[ri], __int_as_float(bi3[ri]));
            }
    }
    __syncthreads();

    // ---- margin-gated exact fp32 rescore: one warp per query ----
    {
        const float2* cand = (const float2*)(smem + SM_CAND);
        int* bestk = (int*)(smem + SM_BESTK);
        for (int it = 0; it < 8; ++it) {
            const int q = wid * 8 + it;
            float2 c0 = cand[q * 48 + lane];
            float2 c1 = (lane < 16) ? cand[q * 48 + 32 + lane]
                                    : make_float2(3.4e38f, __int_as_float(0));
            float lm = fminf(c0.x, c1.x);
            #pragma unroll
            for (int off = 16; off; off >>= 1)
                lm = fminf(lm, __shfl_xor_sync(0xffffffffu, lm, off));
            const float thresh = lm + TAU;

            const float4* er = (const float4*)(enc + (size_t)(m0 + q) * DIMS);
            float bm = 3.4e38f; int bk = 0x7fffffff;
            #pragma unroll
            for (int rnd = 0; rnd < 2; ++rnd) {
                float2 cc = rnd ? c1 : c0;
                if (cc.x <= thresh) {
                    const int k = __float_as_int(cc.y);
                    const float4* cr = (const float4*)(cb + (size_t)k * DIMS);
                    float s = 0.f;
                    #pragma unroll
                    for (int u = 0; u < 16; ++u) {
                        float4 a = er[u], b = cr[u];
                        s = fmaf(a.x, b.x, s); s = fmaf(a.y, b.y, s);
                        s = fmaf(a.z, b.z, s); s = fmaf(a.w, b.w, s);
                    }
                    float m = fmaf(-2.f, s, g_csq[k]);
                    if (m < bm || (m == bm && k < bk)) { bm = m; bk = k; }
                }
            }
            #pragma unroll
            for (int off = 16; off; off >>= 1) {
                float om = __shfl_xor_sync(0xffffffffu, bm, off);
                int   ok = __shfl_xor_sync(0xffffffffu, bk, off);
                if (om < bm || (om == bm && ok < bk)) { bm = om; bk = ok; }
            }
            if (lane == 0) bestk[q] = bk;
        }
    }
    __syncthreads();

    // ---- gather output rows ----
    {
        const int* bestk = (const int*)(smem + SM_BESTK);
        const float4* cb4 = (const float4*)cb;
        float4* out4 = (float4*)out;
        #pragma unroll
        for (int i = 0; i < 4; ++i) {
            int lin = tid + i * THREADS;            // 0..2047
            int q = lin >> 4;
            int quad = lin & 15;
            out4[(size_t)(m0 + q) * 16 + quad] = cb4[(size_t)bestk[q] * 16 + quad];
        }
    }
}

extern "C" void kernel_launch(void* const* d_in, const int* in_sizes, int n_in,
                              void* d_out, int out_size) {
    const float* enc = (const float*)d_in[0];
    const float* cb  = (const float*)d_in[1];
    if (n_in >= 2 && in_sizes[0] == K_CB * DIMS && in_sizes[1] == N_Q * DIMS) {
        enc = (const float*)d_in[1];
        cb  = (const float*)d_in[0];
    }
    float* out = (float*)d_out;

    cudaFuncSetAttribute(vq_main, cudaFuncAttributeMaxDynamicSharedMemorySize, SMEM_TOTAL);

    prep_kernel<<<CONV_BLOCKS + CSQ_BLOCKS, 256>>>(enc, cb);
    vq_main<<<N_Q / MT, THREADS, SMEM_TOTAL>>>(enc, cb, out);
}